// round 2
// baseline (speedup 1.0000x reference)
#include <cuda_runtime.h>
#include <cstdint>

#define NB 32
#define NS 2048
#define ENC2 1024
#define DEC 1024
#define ATT 1024

#define BM 128
#define BN 128
#define BK 32
#define ASTR 36    // smem row stride (floats) for A [m][k], conflict-free fragment loads
#define BSTR 132   // smem row stride (floats) for B [k][n]
#define SMEM_BYTES ((2*BM*ASTR + 2*BK*BSTR) * 4)

// scratch (no allocations allowed)
__device__ float g_dp[NB * ATT];       // decoder_proj + b_dec + b_enc
__device__ float g_energy[NB * NS];    // accumulated energies (b_e omitted: softmax-invariant)

// ---------------------------------------------------------------------------
// Kernel 1: dec_proj[b][a] = sum_d dh[b][d] * W_dec[d][a] + b_dec[a] + b_enc[a]
//           also zeroes g_energy for this launch (graph replays must be clean).
// grid (8 a-chunks of 128, 4 b-chunks of 8), 128 threads.
// ---------------------------------------------------------------------------
__global__ void k_decproj(const float* __restrict__ dh,
                          const float* __restrict__ Wd,
                          const float* __restrict__ bd,
                          const float* __restrict__ ben) {
    __shared__ float sdh[8][DEC];
    const int a  = blockIdx.x * 128 + threadIdx.x;
    const int b0 = blockIdx.y * 8;

    for (int i = threadIdx.x; i < 8 * DEC; i += 128)
        sdh[i >> 10][i & 1023] = dh[(b0 + (i >> 10)) * DEC + (i & 1023)];
    __syncthreads();

    float acc[8];
#pragma unroll
    for (int bb = 0; bb < 8; bb++) acc[bb] = 0.f;

#pragma unroll 4
    for (int d = 0; d < DEC; d++) {
        const float w = Wd[d * ATT + a];
#pragma unroll
        for (int bb = 0; bb < 8; bb++) acc[bb] += w * sdh[bb][d];
    }
    const float bias = bd[a] + ben[a];
#pragma unroll
    for (int bb = 0; bb < 8; bb++)
        g_dp[(b0 + bb) * ATT + a] = acc[bb] + bias;

    // zero energy: 65536 elems over 32 blocks * 128 threads
    const int tid = (blockIdx.y * gridDim.x + blockIdx.x) * 128 + threadIdx.x;
    for (int i = tid; i < NB * NS; i += 32 * 128) g_energy[i] = 0.f;
}

// ---------------------------------------------------------------------------
// Kernel 2: fused energy GEMM.
//   proj = enc(65536x1024) @ W_enc(1024x1024)   [tf32 mma.sync, fp32 accum]
//   epilogue: energy[row] += sum_n tanh(proj + dp[b][n]) * w_e[n]  (atomicAdd)
// CTA tile 128x128, K-step 32, double-buffered smem, 8 warps (4x2).
// Each M-tile lies entirely within one batch b (2048 % 128 == 0).
// ---------------------------------------------------------------------------
__device__ __forceinline__ uint32_t f2tf32(float f) {
    uint32_t u;
    asm("cvt.rna.tf32.f32 %0, %1;" : "=r"(u) : "f"(f));
    return u;
}

__global__ __launch_bounds__(256)
void k_energy(const float* __restrict__ enc,
              const float* __restrict__ We,
              const float* __restrict__ we_v) {
    extern __shared__ uint32_t sh[];
    uint32_t* As = sh;                          // [2][BM][ASTR]
    uint32_t* Bs = sh + 2 * BM * ASTR;          // [2][BK][BSTR]

    const int tm = blockIdx.x;                  // 0..511 M tile
    const int tn = blockIdx.y;                  // 0..7   N tile
    const int tid  = threadIdx.x;
    const int lane = tid & 31;
    const int warp = tid >> 5;
    const int wm = warp >> 1;                   // 0..3
    const int wn = warp & 1;                    // 0..1

    const float* Ag = enc + (size_t)tm * BM * ENC2;
    const float* Bg = We + tn * BN;

    float acc[2][8][4];
#pragma unroll
    for (int i = 0; i < 2; i++)
#pragma unroll
        for (int j = 0; j < 8; j++)
#pragma unroll
            for (int k = 0; k < 4; k++) acc[i][j][k] = 0.f;

    // --- load tile kt=0 into buffer 0 ---
    {
#pragma unroll
        for (int i = 0; i < 4; i++) {
            int idx = i * 256 + tid;
            int row = idx >> 3, c4 = idx & 7;
            float4 v = *(const float4*)(Ag + row * ENC2 + c4 * 4);
            uint4 u = {f2tf32(v.x), f2tf32(v.y), f2tf32(v.z), f2tf32(v.w)};
            *(uint4*)&As[row * ASTR + c4 * 4] = u;
        }
#pragma unroll
        for (int i = 0; i < 4; i++) {
            int idx = i * 256 + tid;
            int row = idx >> 5, c4 = idx & 31;
            float4 v = *(const float4*)(Bg + (size_t)row * ATT + c4 * 4);
            uint4 u = {f2tf32(v.x), f2tf32(v.y), f2tf32(v.z), f2tf32(v.w)};
            *(uint4*)&Bs[row * BSTR + c4 * 4] = u;
        }
    }
    __syncthreads();

    const int NKT = ENC2 / BK;  // 32
    for (int kt = 0; kt < NKT; kt++) {
        float4 pa[4], pb[4];
        if (kt < NKT - 1) {
            const int k0 = (kt + 1) * BK;
#pragma unroll
            for (int i = 0; i < 4; i++) {
                int idx = i * 256 + tid;
                int row = idx >> 3, c4 = idx & 7;
                pa[i] = *(const float4*)(Ag + row * ENC2 + k0 + c4 * 4);
            }
#pragma unroll
            for (int i = 0; i < 4; i++) {
                int idx = i * 256 + tid;
                int row = idx >> 5, c4 = idx & 31;
                pb[i] = *(const float4*)(Bg + (size_t)(k0 + row) * ATT + c4 * 4);
            }
        }

        // ---- compute on buffer kt&1 ----
        const int buf = kt & 1;
        const uint32_t* Ab = As + buf * BM * ASTR + (wm * 32) * ASTR;
        const uint32_t* Bb = Bs + buf * BK * BSTR + wn * 64;
        const int r = lane >> 2, c = lane & 3;
#pragma unroll
        for (int ks = 0; ks < 4; ks++) {
            uint32_t af[2][4];
#pragma unroll
            for (int mt = 0; mt < 2; mt++) {
                const uint32_t* Ap = Ab + (mt * 16 + r) * ASTR + ks * 8 + c;
                af[mt][0] = Ap[0];
                af[mt][1] = Ap[8 * ASTR];
                af[mt][2] = Ap[4];
                af[mt][3] = Ap[8 * ASTR + 4];
            }
            uint32_t bf[8][2];
#pragma unroll
            for (int nt = 0; nt < 8; nt++) {
                const uint32_t* Bp = Bb + (ks * 8 + c) * BSTR + nt * 8 + r;
                bf[nt][0] = Bp[0];
                bf[nt][1] = Bp[4 * BSTR];
            }
#pragma unroll
            for (int mt = 0; mt < 2; mt++)
#pragma unroll
                for (int nt = 0; nt < 8; nt++) {
                    float* d = acc[mt][nt];
                    asm volatile(
                        "mma.sync.aligned.m16n8k8.row.col.f32.tf32.tf32.f32 "
                        "{%0,%1,%2,%3}, {%4,%5,%6,%7}, {%8,%9}, {%0,%1,%2,%3};"
                        : "+f"(d[0]), "+f"(d[1]), "+f"(d[2]), "+f"(d[3])
                        : "r"(af[mt][0]), "r"(af[mt][1]), "r"(af[mt][2]), "r"(af[mt][3]),
                          "r"(bf[nt][0]), "r"(bf[nt][1]));
                }
        }

        if (kt < NKT - 1) {
            const int nb = buf ^ 1;
#pragma unroll
            for (int i = 0; i < 4; i++) {
                int idx = i * 256 + tid;
                int row = idx >> 3, c4 = idx & 7;
                uint4 u = {f2tf32(pa[i].x), f2tf32(pa[i].y), f2tf32(pa[i].z), f2tf32(pa[i].w)};
                *(uint4*)&As[nb * BM * ASTR + row * ASTR + c4 * 4] = u;
            }
#pragma unroll
            for (int i = 0; i < 4; i++) {
                int idx = i * 256 + tid;
                int row = idx >> 5, c4 = idx & 31;
                uint4 u = {f2tf32(pb[i].x), f2tf32(pb[i].y), f2tf32(pb[i].z), f2tf32(pb[i].w)};
                *(uint4*)&Bs[nb * BK * BSTR + row * BSTR + c4 * 4] = u;
            }
            __syncthreads();
        }
    }

    // ---- epilogue: tanh, weight by w_e, row-reduce, atomic into g_energy ----
    const int b = tm >> 4;   // tm*128/2048
    const float* dpp = g_dp + b * ATT + tn * BN + wn * 64;
    const float* wep = we_v + tn * BN + wn * 64;
    const int r = lane >> 2, c = lane & 3;

#pragma unroll
    for (int mt = 0; mt < 2; mt++) {
#pragma unroll
        for (int rr = 0; rr < 2; rr++) {
            float rsum = 0.f;
#pragma unroll
            for (int nt = 0; nt < 8; nt++) {
#pragma unroll
                for (int cc = 0; cc < 2; cc++) {
                    const int col = nt * 8 + c * 2 + cc;
                    const float x = acc[mt][nt][rr * 2 + cc] + dpp[col];
                    rsum += tanhf(x) * wep[col];
                }
            }
            rsum += __shfl_xor_sync(0xffffffffu, rsum, 1);
            rsum += __shfl_xor_sync(0xffffffffu, rsum, 2);
            if (c == 0) {
                const int row = tm * BM + wm * 32 + mt * 16 + rr * 8 + r;
                atomicAdd(&g_energy[row], rsum);
            }
        }
    }
}

// ---------------------------------------------------------------------------
// Kernel 3a: masked softmax over S per batch. 32 blocks x 1024 threads.
// mask arrives as int32 (bool inputs are widened by the harness).
// ---------------------------------------------------------------------------
__global__ void k_softmax(const int* __restrict__ mask,
                          float* __restrict__ out_w) {
    const int b = blockIdx.x, t = threadIdx.x;
    __shared__ float red[32];
    const float NEG = __int_as_float(0xff800000);

    float e0 = g_energy[b * NS + t];
    float e1 = g_energy[b * NS + 1024 + t];
    bool m0 = mask[b * NS + t] != 0;
    bool m1 = mask[b * NS + 1024 + t] != 0;

    float v = fmaxf(m0 ? e0 : NEG, m1 ? e1 : NEG);
#pragma unroll
    for (int o = 16; o; o >>= 1) v = fmaxf(v, __shfl_xor_sync(0xffffffffu, v, o));
    if ((t & 31) == 0) red[t >> 5] = v;
    __syncthreads();
    if (t < 32) {
        float x = red[t];
#pragma unroll
        for (int o = 16; o; o >>= 1) x = fmaxf(x, __shfl_xor_sync(0xffffffffu, x, o));
        red[t] = x;
    }
    __syncthreads();
    const float mx = red[0];
    __syncthreads();

    float x0 = m0 ? __expf(e0 - mx) : 0.f;
    float x1 = m1 ? __expf(e1 - mx) : 0.f;
    float s = x0 + x1;
#pragma unroll
    for (int o = 16; o; o >>= 1) s += __shfl_xor_sync(0xffffffffu, s, o);
    if ((t & 31) == 0) red[t >> 5] = s;
    __syncthreads();
    if (t < 32) {
        float x = red[t];
#pragma unroll
        for (int o = 16; o; o >>= 1) x += __shfl_xor_sync(0xffffffffu, x, o);
        red[t] = x;
    }
    __syncthreads();
    const float inv = 1.0f / red[0];

    out_w[b * NS + t]        = x0 * inv;
    out_w[b * NS + 1024 + t] = x1 * inv;
}

// ---------------------------------------------------------------------------
// Kernel 3b: context[b][e] = sum_s w[b][s] * enc[b][s][e].
// grid (32 b, 8 e-chunks of 128), 256 threads (2 s-stripes x 128 e).
// ---------------------------------------------------------------------------
__global__ void k_context(const float* __restrict__ enc,
                          const float* __restrict__ w,
                          float* __restrict__ out_ctx) {
    const int b = blockIdx.x;
    const int e = blockIdx.y * 128 + (threadIdx.x & 127);
    const int stripe = threadIdx.x >> 7;

    const float* wp = w + b * NS;
    const float* ep = enc + ((size_t)b * NS) * ENC2 + e;

    float a0 = 0.f, a1 = 0.f, a2 = 0.f, a3 = 0.f;
    for (int s = stripe; s < NS; s += 8) {
        a0 += wp[s]     * ep[(size_t)(s)     * ENC2];
        a1 += wp[s + 2] * ep[(size_t)(s + 2) * ENC2];
        a2 += wp[s + 4] * ep[(size_t)(s + 4) * ENC2];
        a3 += wp[s + 6] * ep[(size_t)(s + 6) * ENC2];
    }
    float acc = (a0 + a1) + (a2 + a3);

    __shared__ float part[128];
    if (stripe == 1) part[threadIdx.x & 127] = acc;
    __syncthreads();
    if (stripe == 0)
        out_ctx[b * ENC2 + e] = acc + part[threadIdx.x];
}

// ---------------------------------------------------------------------------
extern "C" void kernel_launch(void* const* d_in, const int* in_sizes, int n_in,
                              void* d_out, int out_size) {
    const float* dh    = (const float*)d_in[0];          // (32,1024)
    const float* enc   = (const float*)d_in[1];          // (32,2048,1024)
    const int*   mask  = (const int*)d_in[2];            // (32,2048) bool->int32
    const float* W_enc = (const float*)d_in[3];          // (1024,1024)
    const float* b_enc = (const float*)d_in[4];          // (1024,)
    const float* W_dec = (const float*)d_in[5];          // (1024,1024)
    const float* b_dec = (const float*)d_in[6];          // (1024,)
    const float* w_e   = (const float*)d_in[7];          // (1024,)
    // d_in[8] = b_e : softmax-invariant, intentionally unused.

    float* out_ctx = (float*)d_out;                  // (32,1024)
    float* out_w   = (float*)d_out + NB * ENC2;      // (32,2048)

    cudaFuncSetAttribute(k_energy, cudaFuncAttributeMaxDynamicSharedMemorySize,
                         SMEM_BYTES);

    k_decproj<<<dim3(8, 4), 128>>>(dh, W_dec, b_dec, b_enc);
    k_energy<<<dim3(512, 8), 256, SMEM_BYTES>>>(enc, W_enc, w_e);
    k_softmax<<<32, 1024>>>(mask, out_w);
    k_context<<<dim3(32, 8), 256>>>(enc, out_w, out_ctx);
}

// round 4
// speedup vs baseline: 1.6197x; 1.6197x over previous
#include <cuda_runtime.h>
#include <cuda_fp16.h>
#include <cstdint>

#define NB 32
#define NS 2048
#define ENC2 1024
#define DEC 1024
#define ATT 1024

#define BM 128
#define BN 128
#define BK 32          // K halfs per chunk
#define ASTRH 40       // A smem row stride in halfs (80B) -> conflict-free frags
#define BSTRH 40       // B smem row stride in halfs

// scratch (no allocations allowed)
__device__ float g_dp[NB * ATT];       // decoder_proj + b_dec + b_enc
__device__ float g_energy[NB * NS];    // energies (b_e dropped: softmax-invariant)
__device__ float g_Wt[ATT * ENC2];     // W_enc transposed: Wt[n][k]

// ---------------------------------------------------------------------------
// Kernel 0: transpose W_enc into g_Wt (n-major, k contiguous)
// ---------------------------------------------------------------------------
__global__ void k_transpose(const float* __restrict__ W) {
    __shared__ float t[32][33];
    const int x = blockIdx.x * 32 + threadIdx.x;   // n
    const int y0 = blockIdx.y * 32;                // k base
    for (int j = threadIdx.y; j < 32; j += 8)
        t[j][threadIdx.x] = W[(y0 + j) * ATT + x];
    __syncthreads();
    const int k = blockIdx.y * 32 + threadIdx.x;
    const int n0 = blockIdx.x * 32;
    for (int j = threadIdx.y; j < 32; j += 8)
        g_Wt[(size_t)(n0 + j) * ENC2 + k] = t[threadIdx.x][j];
}

// ---------------------------------------------------------------------------
// Kernel 1: dec_proj + bias fold; also zero g_energy (graph-replay clean).
// ---------------------------------------------------------------------------
__global__ void k_decproj(const float* __restrict__ dh,
                          const float* __restrict__ Wd,
                          const float* __restrict__ bd,
                          const float* __restrict__ ben) {
    __shared__ float sdh[8][DEC];
    const int a  = blockIdx.x * 128 + threadIdx.x;
    const int b0 = blockIdx.y * 8;

    for (int i = threadIdx.x; i < 8 * DEC; i += 128)
        sdh[i >> 10][i & 1023] = dh[(b0 + (i >> 10)) * DEC + (i & 1023)];
    __syncthreads();

    float acc[8];
#pragma unroll
    for (int bb = 0; bb < 8; bb++) acc[bb] = 0.f;
#pragma unroll 4
    for (int d = 0; d < DEC; d++) {
        const float w = Wd[d * ATT + a];
#pragma unroll
        for (int bb = 0; bb < 8; bb++) acc[bb] += w * sdh[bb][d];
    }
    const float bias = bd[a] + ben[a];
#pragma unroll
    for (int bb = 0; bb < 8; bb++)
        g_dp[(b0 + bb) * ATT + a] = acc[bb] + bias;

    const int tid = (blockIdx.y * gridDim.x + blockIdx.x) * 128 + threadIdx.x;
    for (int i = tid; i < NB * NS; i += 32 * 128) g_energy[i] = 0.f;
}

// ---------------------------------------------------------------------------
// Kernel 2: fused energy GEMM on fp16 mma.sync (m16n8k16, fp32 accum).
//   proj = enc(65536x1024) @ W_enc(1024x1024)
//   epilogue: energy[row] += sum_n tanh(proj + dp[b][n]) * w_e[n]
// CTA 128x128, K-chunk 32, double buffered, 8 warps (4x2), 2 CTAs/SM.
// ---------------------------------------------------------------------------
__device__ __forceinline__ uint2 f4_to_h4(float4 v) {
    half2 lo = __float22half2_rn(make_float2(v.x, v.y));
    half2 hi = __float22half2_rn(make_float2(v.z, v.w));
    uint2 u;
    u.x = *(uint32_t*)&lo;
    u.y = *(uint32_t*)&hi;
    return u;
}

__global__ __launch_bounds__(256, 2)
void k_energy(const float* __restrict__ enc,
              const float* __restrict__ we_v) {
    __shared__ __align__(16) __half As[2][BM * ASTRH];
    __shared__ __align__(16) __half Bs[2][BN * BSTRH];

    const int tm = blockIdx.x;                  // 0..511 M tile
    const int tn = blockIdx.y;                  // 0..7   N tile
    const int tid  = threadIdx.x;
    const int lane = tid & 31;
    const int warp = tid >> 5;
    const int wm = warp >> 1;                   // 0..3
    const int wn = warp & 1;                    // 0..1

    const float* Ag = enc + (size_t)tm * BM * ENC2;
    const float* Bg = g_Wt + (size_t)tn * BN * ENC2;

    float acc[2][8][4];
#pragma unroll
    for (int i = 0; i < 2; i++)
#pragma unroll
        for (int j = 0; j < 8; j++)
#pragma unroll
            for (int k = 0; k < 4; k++) acc[i][j][k] = 0.f;

    // per-thread tile-load coordinates: 1024 float4 per tile, 4 per thread
    // idx = i*256 + tid; row = idx>>3 (0..127), c4 = idx&7 (float4 within row)

    // --- load chunk 0 into buffer 0 ---
#pragma unroll
    for (int i = 0; i < 4; i++) {
        int idx = i * 256 + tid;
        int row = idx >> 3, c4 = idx & 7;
        float4 va = *(const float4*)(Ag + row * ENC2 + c4 * 4);
        *(uint2*)&As[0][row * ASTRH + c4 * 4] = f4_to_h4(va);
        float4 vb = *(const float4*)(Bg + (size_t)row * ENC2 + c4 * 4);
        *(uint2*)&Bs[0][row * BSTRH + c4 * 4] = f4_to_h4(vb);
    }
    __syncthreads();

    const int NKT = ENC2 / BK;  // 32
    for (int kt = 0; kt < NKT; kt++) {
        float4 pa[4], pb[4];
        if (kt < NKT - 1) {
            const int k0 = (kt + 1) * BK;
#pragma unroll
            for (int i = 0; i < 4; i++) {
                int idx = i * 256 + tid;
                int row = idx >> 3, c4 = idx & 7;
                pa[i] = *(const float4*)(Ag + row * ENC2 + k0 + c4 * 4);
                pb[i] = *(const float4*)(Bg + (size_t)row * ENC2 + k0 + c4 * 4);
            }
        }

        // ---- compute on buffer kt&1 ----
        const int buf = kt & 1;
        const uint32_t* Aw = (const uint32_t*)&As[buf][0] + (wm * 32) * (ASTRH / 2);
        const uint32_t* Bw = (const uint32_t*)&Bs[buf][0] + (wn * 64) * (BSTRH / 2);
        const int r = lane >> 2, c = lane & 3;
#pragma unroll
        for (int ks = 0; ks < 2; ks++) {        // k16 step within the 32-chunk
            uint32_t af[2][4];
#pragma unroll
            for (int mt = 0; mt < 2; mt++) {
                const uint32_t* Ap = Aw + (mt * 16 + r) * (ASTRH / 2) + ks * 8 + c;
                af[mt][0] = Ap[0];                    // (r      , k 2c..2c+1)
                af[mt][1] = Ap[8 * (ASTRH / 2)];      // (r+8    , k 2c..2c+1)
                af[mt][2] = Ap[4];                    // (r      , k 2c+8..)
                af[mt][3] = Ap[8 * (ASTRH / 2) + 4];  // (r+8    , k 2c+8..)
            }
            uint32_t bf[8][2];
#pragma unroll
            for (int nt = 0; nt < 8; nt++) {
                const uint32_t* Bp = Bw + (nt * 8 + r) * (BSTRH / 2) + ks * 8 + c;
                bf[nt][0] = Bp[0];                    // (k 2c..2c+1 , n r)
                bf[nt][1] = Bp[4];                    // (k 2c+8..   , n r)
            }
#pragma unroll
            for (int mt = 0; mt < 2; mt++)
#pragma unroll
                for (int nt = 0; nt < 8; nt++) {
                    float* d = acc[mt][nt];
                    asm volatile(
                        "mma.sync.aligned.m16n8k16.row.col.f32.f16.f16.f32 "
                        "{%0,%1,%2,%3}, {%4,%5,%6,%7}, {%8,%9}, {%0,%1,%2,%3};"
                        : "+f"(d[0]), "+f"(d[1]), "+f"(d[2]), "+f"(d[3])
                        : "r"(af[mt][0]), "r"(af[mt][1]), "r"(af[mt][2]), "r"(af[mt][3]),
                          "r"(bf[nt][0]), "r"(bf[nt][1]));
                }
        }

        if (kt < NKT - 1) {
            const int nb = buf ^ 1;
            __syncthreads();   // all reads of buffer nb (from kt-1) are done
#pragma unroll
            for (int i = 0; i < 4; i++) {
                int idx = i * 256 + tid;
                int row = idx >> 3, c4 = idx & 7;
                *(uint2*)&As[nb][row * ASTRH + c4 * 4] = f4_to_h4(pa[i]);
                *(uint2*)&Bs[nb][row * BSTRH + c4 * 4] = f4_to_h4(pb[i]);
            }
            __syncthreads();
        }
    }

    // ---- epilogue: tanh, weight by w_e, row-reduce, atomic into g_energy ----
    const int b = tm >> 4;   // 16 M-tiles per batch
    __syncthreads();
    float* dp_s = (float*)&As[0][0];
    float* we_s = dp_s + BN;
    if (tid < BN) {
        dp_s[tid] = g_dp[b * ATT + tn * BN + tid];
        we_s[tid] = we_v[tn * BN + tid];
    }
    __syncthreads();

    const int r = lane >> 2, c = lane & 3;
    const float* dpp = dp_s + wn * 64;
    const float* wep = we_s + wn * 64;

#pragma unroll
    for (int mt = 0; mt < 2; mt++) {
#pragma unroll
        for (int rr = 0; rr < 2; rr++) {
            float rsum = 0.f;
#pragma unroll
            for (int nt = 0; nt < 8; nt++) {
#pragma unroll
                for (int cc = 0; cc < 2; cc++) {
                    const int col = nt * 8 + c * 2 + cc;
                    const float x = acc[mt][nt][rr * 2 + cc] + dpp[col];
                    rsum += tanhf(x) * wep[col];
                }
            }
            rsum += __shfl_xor_sync(0xffffffffu, rsum, 1);
            rsum += __shfl_xor_sync(0xffffffffu, rsum, 2);
            if (c == 0) {
                const int row = tm * BM + wm * 32 + mt * 16 + rr * 8 + r;
                atomicAdd(&g_energy[row], rsum);
            }
        }
    }
}

// ---------------------------------------------------------------------------
// Kernel 3a: masked softmax (mask = int32). Also zeroes out_ctx for 3b atomics.
// ---------------------------------------------------------------------------
__global__ void k_softmax(const int* __restrict__ mask,
                          float* __restrict__ out_w,
                          float* __restrict__ out_ctx) {
    const int b = blockIdx.x, t = threadIdx.x;
    __shared__ float red[32];
    const float NEG = __int_as_float(0xff800000);

    out_ctx[b * ENC2 + t] = 0.f;

    float e0 = g_energy[b * NS + t];
    float e1 = g_energy[b * NS + 1024 + t];
    bool m0 = mask[b * NS + t] != 0;
    bool m1 = mask[b * NS + 1024 + t] != 0;

    float v = fmaxf(m0 ? e0 : NEG, m1 ? e1 : NEG);
#pragma unroll
    for (int o = 16; o; o >>= 1) v = fmaxf(v, __shfl_xor_sync(0xffffffffu, v, o));
    if ((t & 31) == 0) red[t >> 5] = v;
    __syncthreads();
    if (t < 32) {
        float x = red[t];
#pragma unroll
        for (int o = 16; o; o >>= 1) x = fmaxf(x, __shfl_xor_sync(0xffffffffu, x, o));
        red[t] = x;
    }
    __syncthreads();
    const float mx = red[0];
    __syncthreads();

    float x0 = m0 ? __expf(e0 - mx) : 0.f;
    float x1 = m1 ? __expf(e1 - mx) : 0.f;
    float s = x0 + x1;
#pragma unroll
    for (int o = 16; o; o >>= 1) s += __shfl_xor_sync(0xffffffffu, s, o);
    if ((t & 31) == 0) red[t >> 5] = s;
    __syncthreads();
    if (t < 32) {
        float x = red[t];
#pragma unroll
        for (int o = 16; o; o >>= 1) x += __shfl_xor_sync(0xffffffffu, x, o);
        red[t] = x;
    }
    __syncthreads();
    const float inv = 1.0f / red[0];

    out_w[b * NS + t]        = x0 * inv;
    out_w[b * NS + 1024 + t] = x1 * inv;
}

// ---------------------------------------------------------------------------
// Kernel 3b: context, split-S x4 with atomics for MLP/occupancy.
// grid (32 b, 8 e-chunks, 4 s-chunks), 256 threads.
// ---------------------------------------------------------------------------
__global__ void k_context(const float* __restrict__ enc,
                          const float* __restrict__ w,
                          float* __restrict__ out_ctx) {
    const int b = blockIdx.x;
    const int e = blockIdx.y * 128 + (threadIdx.x & 127);
    const int stripe = threadIdx.x >> 7;
    const int s0 = blockIdx.z * 512;

    const float* wp = w + b * NS;
    const float* ep = enc + ((size_t)b * NS) * ENC2 + e;

    float a0 = 0.f, a1 = 0.f, a2 = 0.f, a3 = 0.f;
    for (int s = s0 + stripe; s < s0 + 512; s += 8) {
        a0 += wp[s]     * ep[(size_t)(s)     * ENC2];
        a1 += wp[s + 2] * ep[(size_t)(s + 2) * ENC2];
        a2 += wp[s + 4] * ep[(size_t)(s + 4) * ENC2];
        a3 += wp[s + 6] * ep[(size_t)(s + 6) * ENC2];
    }
    float acc = (a0 + a1) + (a2 + a3);

    __shared__ float part[128];
    if (stripe == 1) part[threadIdx.x & 127] = acc;
    __syncthreads();
    if (stripe == 0)
        atomicAdd(&out_ctx[b * ENC2 + e], acc + part[threadIdx.x]);
}

// ---------------------------------------------------------------------------
extern "C" void kernel_launch(void* const* d_in, const int* in_sizes, int n_in,
                              void* d_out, int out_size) {
    const float* dh    = (const float*)d_in[0];
    const float* enc   = (const float*)d_in[1];
    const int*   mask  = (const int*)d_in[2];
    const float* W_enc = (const float*)d_in[3];
    const float* b_enc = (const float*)d_in[4];
    const float* W_dec = (const float*)d_in[5];
    const float* b_dec = (const float*)d_in[6];
    const float* w_e   = (const float*)d_in[7];
    // d_in[8] = b_e : softmax-invariant, unused.

    float* out_ctx = (float*)d_out;
    float* out_w   = (float*)d_out + NB * ENC2;

    k_transpose<<<dim3(32, 32), dim3(32, 8)>>>(W_enc);
    k_decproj<<<dim3(8, 4), 128>>>(dh, W_dec, b_dec, b_enc);
    k_energy<<<dim3(512, 8), 256>>>(enc, w_e);
    k_softmax<<<32, 1024>>>(mask, out_w, out_ctx);
    k_context<<<dim3(32, 8, 4), 256>>>(enc, out_w, out_ctx);
}

// round 5
// speedup vs baseline: 1.6456x; 1.0160x over previous
#include <cuda_runtime.h>
#include <cuda_fp16.h>
#include <cstdint>

#define NB 32
#define NS 2048
#define ENC2 1024
#define DEC 1024
#define ATT 1024

#define BM 128
#define BN 128
#define BK 32          // K halfs per chunk
#define ASTRH 40       // A smem row stride in halfs (80B) -> conflict-free frags
#define BSTRH 40       // B smem row stride in halfs

// scratch (no allocations allowed)
__device__ float g_dp[NB * ATT];       // decoder_proj + b_dec + b_enc
__device__ float g_energy[NB * NS];    // energies (b_e dropped: softmax-invariant)
__device__ float g_Wt[ATT * ENC2];     // W_enc transposed: Wt[n][k]

// ---------------------------------------------------------------------------
// Kernel 0: transpose W_enc into g_Wt (n-major, k contiguous)
// ---------------------------------------------------------------------------
__global__ void k_transpose(const float* __restrict__ W) {
    __shared__ float t[32][33];
    const int x = blockIdx.x * 32 + threadIdx.x;   // n
    const int y0 = blockIdx.y * 32;                // k base
    for (int j = threadIdx.y; j < 32; j += 8)
        t[j][threadIdx.x] = W[(y0 + j) * ATT + x];
    __syncthreads();
    const int k = blockIdx.y * 32 + threadIdx.x;
    const int n0 = blockIdx.x * 32;
    for (int j = threadIdx.y; j < 32; j += 8)
        g_Wt[(size_t)(n0 + j) * ENC2 + k] = t[threadIdx.x][j];
}

// ---------------------------------------------------------------------------
// Kernel 1: dec_proj + bias fold; also zero g_energy (graph-replay clean).
// ---------------------------------------------------------------------------
__global__ void k_decproj(const float* __restrict__ dh,
                          const float* __restrict__ Wd,
                          const float* __restrict__ bd,
                          const float* __restrict__ ben) {
    __shared__ float sdh[8][DEC];
    const int a  = blockIdx.x * 128 + threadIdx.x;
    const int b0 = blockIdx.y * 8;

    for (int i = threadIdx.x; i < 8 * DEC; i += 128)
        sdh[i >> 10][i & 1023] = dh[(b0 + (i >> 10)) * DEC + (i & 1023)];
    __syncthreads();

    float acc[8];
#pragma unroll
    for (int bb = 0; bb < 8; bb++) acc[bb] = 0.f;
#pragma unroll 4
    for (int d = 0; d < DEC; d++) {
        const float w = Wd[d * ATT + a];
#pragma unroll
        for (int bb = 0; bb < 8; bb++) acc[bb] += w * sdh[bb][d];
    }
    const float bias = bd[a] + ben[a];
#pragma unroll
    for (int bb = 0; bb < 8; bb++)
        g_dp[(b0 + bb) * ATT + a] = acc[bb] + bias;

    const int tid = (blockIdx.y * gridDim.x + blockIdx.x) * 128 + threadIdx.x;
    for (int i = tid; i < NB * NS; i += 32 * 128) g_energy[i] = 0.f;
}

// ---------------------------------------------------------------------------
// Kernel 2: fused energy GEMM on fp16 mma.sync (m16n8k16, fp32 accum).
//   proj = enc(65536x1024) @ W_enc(1024x1024)
//   epilogue: energy[row] += sum_n tanh(proj + dp[b][n]) * w_e[n]
// CTA 128x128, K-chunk 32, double buffered, 8 warps (4x2), 2 CTAs/SM.
// Grid: tn FASTEST so 8 CTAs sharing an A tile are concurrent (L2 reuse).
// ---------------------------------------------------------------------------
__device__ __forceinline__ uint2 f4_to_h4(float4 v) {
    half2 lo = __float22half2_rn(make_float2(v.x, v.y));
    half2 hi = __float22half2_rn(make_float2(v.z, v.w));
    uint2 u;
    u.x = *(uint32_t*)&lo;
    u.y = *(uint32_t*)&hi;
    return u;
}

__global__ __launch_bounds__(256, 2)
void k_energy(const float* __restrict__ enc,
              const float* __restrict__ we_v) {
    __shared__ __align__(16) __half As[2][BM * ASTRH];
    __shared__ __align__(16) __half Bs[2][BN * BSTRH];

    const int tn = blockIdx.x;                  // 0..7   N tile (fastest)
    const int tm = blockIdx.y;                  // 0..511 M tile
    const int tid  = threadIdx.x;
    const int lane = tid & 31;
    const int warp = tid >> 5;
    const int wm = warp >> 1;                   // 0..3
    const int wn = warp & 1;                    // 0..1

    const float* Ag = enc + (size_t)tm * BM * ENC2;
    const float* Bg = g_Wt + (size_t)tn * BN * ENC2;

    float acc[2][8][4];
#pragma unroll
    for (int i = 0; i < 2; i++)
#pragma unroll
        for (int j = 0; j < 8; j++)
#pragma unroll
            for (int k = 0; k < 4; k++) acc[i][j][k] = 0.f;

    // --- load chunk 0 into buffer 0 ---
#pragma unroll
    for (int i = 0; i < 4; i++) {
        int idx = i * 256 + tid;
        int row = idx >> 3, c4 = idx & 7;
        float4 va = *(const float4*)(Ag + row * ENC2 + c4 * 4);
        *(uint2*)&As[0][row * ASTRH + c4 * 4] = f4_to_h4(va);
        float4 vb = *(const float4*)(Bg + (size_t)row * ENC2 + c4 * 4);
        *(uint2*)&Bs[0][row * BSTRH + c4 * 4] = f4_to_h4(vb);
    }
    __syncthreads();

    const int NKT = ENC2 / BK;  // 32
    for (int kt = 0; kt < NKT; kt++) {
        float4 pa[4], pb[4];
        if (kt < NKT - 1) {
            const int k0 = (kt + 1) * BK;
#pragma unroll
            for (int i = 0; i < 4; i++) {
                int idx = i * 256 + tid;
                int row = idx >> 3, c4 = idx & 7;
                pa[i] = *(const float4*)(Ag + row * ENC2 + k0 + c4 * 4);
                pb[i] = *(const float4*)(Bg + (size_t)row * ENC2 + k0 + c4 * 4);
            }
        }

        // ---- compute on buffer kt&1 ----
        const int buf = kt & 1;
        const uint32_t* Aw = (const uint32_t*)&As[buf][0] + (wm * 32) * (ASTRH / 2);
        const uint32_t* Bw = (const uint32_t*)&Bs[buf][0] + (wn * 64) * (BSTRH / 2);
        const int r = lane >> 2, c = lane & 3;
#pragma unroll
        for (int ks = 0; ks < 2; ks++) {        // k16 step within the 32-chunk
            uint32_t af[2][4];
#pragma unroll
            for (int mt = 0; mt < 2; mt++) {
                const uint32_t* Ap = Aw + (mt * 16 + r) * (ASTRH / 2) + ks * 8 + c;
                af[mt][0] = Ap[0];
                af[mt][1] = Ap[8 * (ASTRH / 2)];
                af[mt][2] = Ap[4];
                af[mt][3] = Ap[8 * (ASTRH / 2) + 4];
            }
            uint32_t bf[8][2];
#pragma unroll
            for (int nt = 0; nt < 8; nt++) {
                const uint32_t* Bp = Bw + (nt * 8 + r) * (BSTRH / 2) + ks * 8 + c;
                bf[nt][0] = Bp[0];
                bf[nt][1] = Bp[4];
            }
#pragma unroll
            for (int mt = 0; mt < 2; mt++)
#pragma unroll
                for (int nt = 0; nt < 8; nt++) {
                    float* d = acc[mt][nt];
                    asm volatile(
                        "mma.sync.aligned.m16n8k16.row.col.f32.f16.f16.f32 "
                        "{%0,%1,%2,%3}, {%4,%5,%6,%7}, {%8,%9}, {%0,%1,%2,%3};"
                        : "+f"(d[0]), "+f"(d[1]), "+f"(d[2]), "+f"(d[3])
                        : "r"(af[mt][0]), "r"(af[mt][1]), "r"(af[mt][2]), "r"(af[mt][3]),
                          "r"(bf[nt][0]), "r"(bf[nt][1]));
                }
        }

        if (kt < NKT - 1) {
            // stores go to buffer nb; its last readers finished at the sync
            // that ended chunk kt-1, so no pre-store barrier is needed.
            const int nb = buf ^ 1;
#pragma unroll
            for (int i = 0; i < 4; i++) {
                int idx = i * 256 + tid;
                int row = idx >> 3, c4 = idx & 7;
                *(uint2*)&As[nb][row * ASTRH + c4 * 4] = f4_to_h4(pa[i]);
                *(uint2*)&Bs[nb][row * BSTRH + c4 * 4] = f4_to_h4(pb[i]);
            }
            __syncthreads();
        }
    }

    // ---- epilogue: tanh, weight by w_e, row-reduce, atomic into g_energy ----
    const int b = tm >> 4;   // 16 M-tiles per batch
    __syncthreads();
    float* dp_s = (float*)&As[0][0];
    float* we_s = dp_s + BN;
    if (tid < BN) {
        dp_s[tid] = g_dp[b * ATT + tn * BN + tid];
        we_s[tid] = we_v[tn * BN + tid];
    }
    __syncthreads();

    const int r = lane >> 2, c = lane & 3;
    const float* dpp = dp_s + wn * 64;
    const float* wep = we_s + wn * 64;

#pragma unroll
    for (int mt = 0; mt < 2; mt++) {
#pragma unroll
        for (int rr = 0; rr < 2; rr++) {
            float rsum = 0.f;
#pragma unroll
            for (int nt = 0; nt < 8; nt++) {
#pragma unroll
                for (int cc = 0; cc < 2; cc++) {
                    const int col = nt * 8 + c * 2 + cc;
                    const float x = acc[mt][nt][rr * 2 + cc] + dpp[col];
                    rsum += tanhf(x) * wep[col];
                }
            }
            rsum += __shfl_xor_sync(0xffffffffu, rsum, 1);
            rsum += __shfl_xor_sync(0xffffffffu, rsum, 2);
            if (c == 0) {
                const int row = tm * BM + wm * 32 + mt * 16 + rr * 8 + r;
                atomicAdd(&g_energy[row], rsum);
            }
        }
    }
}

// ---------------------------------------------------------------------------
// Kernel 3a: masked softmax (mask = int32). Also zeroes out_ctx for 3b atomics.
// ---------------------------------------------------------------------------
__global__ void k_softmax(const int* __restrict__ mask,
                          float* __restrict__ out_w,
                          float* __restrict__ out_ctx) {
    const int b = blockIdx.x, t = threadIdx.x;
    __shared__ float red[32];
    const float NEG = __int_as_float(0xff800000);

    out_ctx[b * ENC2 + t] = 0.f;

    float e0 = g_energy[b * NS + t];
    float e1 = g_energy[b * NS + 1024 + t];
    bool m0 = mask[b * NS + t] != 0;
    bool m1 = mask[b * NS + 1024 + t] != 0;

    float v = fmaxf(m0 ? e0 : NEG, m1 ? e1 : NEG);
#pragma unroll
    for (int o = 16; o; o >>= 1) v = fmaxf(v, __shfl_xor_sync(0xffffffffu, v, o));
    if ((t & 31) == 0) red[t >> 5] = v;
    __syncthreads();
    if (t < 32) {
        float x = red[t];
#pragma unroll
        for (int o = 16; o; o >>= 1) x = fmaxf(x, __shfl_xor_sync(0xffffffffu, x, o));
        red[t] = x;
    }
    __syncthreads();
    const float mx = red[0];
    __syncthreads();

    float x0 = m0 ? __expf(e0 - mx) : 0.f;
    float x1 = m1 ? __expf(e1 - mx) : 0.f;
    float s = x0 + x1;
#pragma unroll
    for (int o = 16; o; o >>= 1) s += __shfl_xor_sync(0xffffffffu, s, o);
    if ((t & 31) == 0) red[t >> 5] = s;
    __syncthreads();
    if (t < 32) {
        float x = red[t];
#pragma unroll
        for (int o = 16; o; o >>= 1) x += __shfl_xor_sync(0xffffffffu, x, o);
        red[t] = x;
    }
    __syncthreads();
    const float inv = 1.0f / red[0];

    out_w[b * NS + t]        = x0 * inv;
    out_w[b * NS + 1024 + t] = x1 * inv;
}

// ---------------------------------------------------------------------------
// Kernel 3b: context, split-S x8 with atomics for MLP/occupancy.
// grid (32 b, 8 e-chunks, 8 s-chunks), 256 threads.
// ---------------------------------------------------------------------------
__global__ void k_context(const float* __restrict__ enc,
                          const float* __restrict__ w,
                          float* __restrict__ out_ctx) {
    const int b = blockIdx.x;
    const int e = blockIdx.y * 128 + (threadIdx.x & 127);
    const int stripe = threadIdx.x >> 7;
    const int s0 = blockIdx.z * 256;

    const float* wp = w + b * NS;
    const float* ep = enc + ((size_t)b * NS) * ENC2 + e;

    float a0 = 0.f, a1 = 0.f, a2 = 0.f, a3 = 0.f;
    for (int s = s0 + stripe; s < s0 + 256; s += 8) {
        a0 += wp[s]     * ep[(size_t)(s)     * ENC2];
        a1 += wp[s + 2] * ep[(size_t)(s + 2) * ENC2];
        a2 += wp[s + 4] * ep[(size_t)(s + 4) * ENC2];
        a3 += wp[s + 6] * ep[(size_t)(s + 6) * ENC2];
    }
    float acc = (a0 + a1) + (a2 + a3);

    __shared__ float part[128];
    if (stripe == 1) part[threadIdx.x & 127] = acc;
    __syncthreads();
    if (stripe == 0)
        atomicAdd(&out_ctx[b * ENC2 + e], acc + part[threadIdx.x]);
}

// ---------------------------------------------------------------------------
extern "C" void kernel_launch(void* const* d_in, const int* in_sizes, int n_in,
                              void* d_out, int out_size) {
    const float* dh    = (const float*)d_in[0];
    const float* enc   = (const float*)d_in[1];
    const int*   mask  = (const int*)d_in[2];
    const float* W_enc = (const float*)d_in[3];
    const float* b_enc = (const float*)d_in[4];
    const float* W_dec = (const float*)d_in[5];
    const float* b_dec = (const float*)d_in[6];
    const float* w_e   = (const float*)d_in[7];
    // d_in[8] = b_e : softmax-invariant, unused.

    float* out_ctx = (float*)d_out;
    float* out_w   = (float*)d_out + NB * ENC2;

    k_transpose<<<dim3(32, 32), dim3(32, 8)>>>(W_enc);
    k_decproj<<<dim3(8, 4), 128>>>(dh, W_dec, b_dec, b_enc);
    k_energy<<<dim3(8, 512), 256>>>(enc, w_e);
    k_softmax<<<32, 1024>>>(mask, out_w, out_ctx);
    k_context<<<dim3(32, 8, 8), 256>>>(enc, out_w, out_ctx);
}

// round 6
// speedup vs baseline: 1.6709x; 1.0154x over previous
#include <cuda_runtime.h>
#include <cuda_fp16.h>
#include <cstdint>

#define NB 32
#define NS 2048
#define ENC2 1024
#define DEC 1024
#define ATT 1024

#define BM 128
#define BN 128
#define BK 32          // K halfs per chunk
#define ASTRH 40       // smem row stride in halfs (80B): conflict-free frags, 16B-aligned rows
#define STG 4          // cp.async pipeline stages

// scratch (no allocations allowed)
__device__ float  g_dp[NB * ATT];                       // decoder_proj + b_dec + b_enc
__device__ float  g_energy[NB * NS];                    // energies (b_e dropped)
__device__ __half g_ench[(size_t)NB * NS * ENC2];       // enc in fp16 (128 MB)
__device__ __half g_Wth[ATT * ENC2];                    // W_enc^T in fp16: Wt[n][k]

__device__ __forceinline__ uint32_t smem_u32(const void* p) {
    uint32_t a;
    asm("{ .reg .u64 t; cvta.to.shared.u64 t, %1; cvt.u32.u64 %0, t; }"
        : "=r"(a) : "l"(p));
    return a;
}
__device__ __forceinline__ uint2 f4_to_h4(float4 v) {
    half2 lo = __float22half2_rn(make_float2(v.x, v.y));
    half2 hi = __float22half2_rn(make_float2(v.z, v.w));
    uint2 u;
    u.x = *(uint32_t*)&lo;
    u.y = *(uint32_t*)&hi;
    return u;
}

// ---------------------------------------------------------------------------
// Kernel 0a: enc fp32 -> fp16 (vectorized grid-stride)
// ---------------------------------------------------------------------------
__global__ void k_convert(const float* __restrict__ enc) {
    const size_t total4 = (size_t)NB * NS * ENC2 / 4;   // 16M float4
    uint2* dst = (uint2*)g_ench;
    const float4* src = (const float4*)enc;
    for (size_t p = (size_t)blockIdx.x * blockDim.x + threadIdx.x;
         p < total4; p += (size_t)gridDim.x * blockDim.x)
        dst[p] = f4_to_h4(src[p]);
}

// ---------------------------------------------------------------------------
// Kernel 0b: transpose W_enc into g_Wth (n-major, k contiguous, fp16)
// ---------------------------------------------------------------------------
__global__ void k_transpose(const float* __restrict__ W) {
    __shared__ float t[32][33];
    const int x = blockIdx.x * 32 + threadIdx.x;   // n
    const int y0 = blockIdx.y * 32;                // k base
    for (int j = threadIdx.y; j < 32; j += 8)
        t[j][threadIdx.x] = W[(y0 + j) * ATT + x];
    __syncthreads();
    const int k = blockIdx.y * 32 + threadIdx.x;
    const int n0 = blockIdx.x * 32;
    for (int j = threadIdx.y; j < 32; j += 8)
        g_Wth[(size_t)(n0 + j) * ENC2 + k] = __float2half(t[threadIdx.x][j]);
}

// ---------------------------------------------------------------------------
// Kernel 1: dec_proj + bias fold; also zero g_energy (graph-replay clean).
// ---------------------------------------------------------------------------
__global__ void k_decproj(const float* __restrict__ dh,
                          const float* __restrict__ Wd,
                          const float* __restrict__ bd,
                          const float* __restrict__ ben) {
    __shared__ float sdh[8][DEC];
    const int a  = blockIdx.x * 128 + threadIdx.x;
    const int b0 = blockIdx.y * 8;

    for (int i = threadIdx.x; i < 8 * DEC; i += 128)
        sdh[i >> 10][i & 1023] = dh[(b0 + (i >> 10)) * DEC + (i & 1023)];
    __syncthreads();

    float acc[8];
#pragma unroll
    for (int bb = 0; bb < 8; bb++) acc[bb] = 0.f;
#pragma unroll 4
    for (int d = 0; d < DEC; d++) {
        const float w = Wd[d * ATT + a];
#pragma unroll
        for (int bb = 0; bb < 8; bb++) acc[bb] += w * sdh[bb][d];
    }
    const float bias = bd[a] + ben[a];
#pragma unroll
    for (int bb = 0; bb < 8; bb++)
        g_dp[(b0 + bb) * ATT + a] = acc[bb] + bias;

    const int tid = (blockIdx.y * gridDim.x + blockIdx.x) * 128 + threadIdx.x;
    for (int i = tid; i < NB * NS; i += 32 * 128) g_energy[i] = 0.f;
}

// ---------------------------------------------------------------------------
// Kernel 2: fused energy GEMM, fp16 mma.sync + 4-stage cp.async ring.
//   proj = enc(65536x1024) @ W_enc(1024x1024), fp32 accum
//   epilogue: energy[row] += sum_n tanh(proj + dp[b][n]) * w_e[n]
// CTA 128x128, K-chunk 32, 8 warps (4x2), 2 CTAs/SM, tn fastest.
// ---------------------------------------------------------------------------
__global__ __launch_bounds__(256, 2)
void k_energy(const float* __restrict__ we_v) {
    __shared__ __align__(16) __half As[STG][BM * ASTRH];
    __shared__ __align__(16) __half Bs[STG][BN * ASTRH];

    const int tn = blockIdx.x;                  // 0..7   N tile (fastest)
    const int tm = blockIdx.y;                  // 0..511 M tile
    const int tid  = threadIdx.x;
    const int lane = tid & 31;
    const int warp = tid >> 5;
    const int wm = warp >> 1;                   // 0..3
    const int wn = warp & 1;                    // 0..1

    const __half* Ag = g_ench + (size_t)tm * BM * ENC2;
    const __half* Bg = g_Wth + (size_t)tn * BN * ENC2;

    float acc[2][8][4];
#pragma unroll
    for (int i = 0; i < 2; i++)
#pragma unroll
        for (int j = 0; j < 8; j++)
#pragma unroll
            for (int k = 0; k < 4; k++) acc[i][j][k] = 0.f;

    // loader: per chunk, 512 x 16B for A + 512 x 16B for B over 256 threads
    auto load_chunk = [&](int kc) {
        const int st = kc & (STG - 1);
        const __half* a = Ag + kc * BK;
        const __half* b = Bg + kc * BK;
#pragma unroll
        for (int j = 0; j < 2; j++) {
            const int idx = tid + j * 256;          // 0..511
            const int row = idx >> 2, c16 = idx & 3;
            const uint32_t da = smem_u32(&As[st][row * ASTRH + c16 * 8]);
            asm volatile("cp.async.cg.shared.global [%0], [%1], 16;"
                         :: "r"(da), "l"(a + (size_t)row * ENC2 + c16 * 8));
            const uint32_t db = smem_u32(&Bs[st][row * ASTRH + c16 * 8]);
            asm volatile("cp.async.cg.shared.global [%0], [%1], 16;"
                         :: "r"(db), "l"(b + (size_t)row * ENC2 + c16 * 8));
        }
        asm volatile("cp.async.commit_group;" ::: "memory");
    };

    load_chunk(0);
    load_chunk(1);
    load_chunk(2);

    const int NKT = ENC2 / BK;  // 32
    for (int kt = 0; kt < NKT; kt++) {
        // chunk kt's group must be complete
        if (kt < NKT - 2)
            asm volatile("cp.async.wait_group 2;" ::: "memory");
        else if (kt == NKT - 2)
            asm volatile("cp.async.wait_group 1;" ::: "memory");
        else
            asm volatile("cp.async.wait_group 0;" ::: "memory");
        __syncthreads();   // data visible to all; stage (kt+3)&3 readers done

        if (kt + 3 < NKT) load_chunk(kt + 3);

        // ---- compute on stage kt&3 ----
        const int st = kt & (STG - 1);
        const uint32_t* Aw = (const uint32_t*)&As[st][0] + (wm * 32) * (ASTRH / 2);
        const uint32_t* Bw = (const uint32_t*)&Bs[st][0] + (wn * 64) * (ASTRH / 2);
        const int r = lane >> 2, c = lane & 3;
#pragma unroll
        for (int ks = 0; ks < 2; ks++) {        // k16 step within the 32-chunk
            uint32_t af[2][4];
#pragma unroll
            for (int mt = 0; mt < 2; mt++) {
                const uint32_t* Ap = Aw + (mt * 16 + r) * (ASTRH / 2) + ks * 8 + c;
                af[mt][0] = Ap[0];
                af[mt][1] = Ap[8 * (ASTRH / 2)];
                af[mt][2] = Ap[4];
                af[mt][3] = Ap[8 * (ASTRH / 2) + 4];
            }
            uint32_t bf[8][2];
#pragma unroll
            for (int nt = 0; nt < 8; nt++) {
                const uint32_t* Bp = Bw + (nt * 8 + r) * (ASTRH / 2) + ks * 8 + c;
                bf[nt][0] = Bp[0];
                bf[nt][1] = Bp[4];
            }
#pragma unroll
            for (int mt = 0; mt < 2; mt++)
#pragma unroll
                for (int nt = 0; nt < 8; nt++) {
                    float* d = acc[mt][nt];
                    asm volatile(
                        "mma.sync.aligned.m16n8k16.row.col.f32.f16.f16.f32 "
                        "{%0,%1,%2,%3}, {%4,%5,%6,%7}, {%8,%9}, {%0,%1,%2,%3};"
                        : "+f"(d[0]), "+f"(d[1]), "+f"(d[2]), "+f"(d[3])
                        : "r"(af[mt][0]), "r"(af[mt][1]), "r"(af[mt][2]), "r"(af[mt][3]),
                          "r"(bf[nt][0]), "r"(bf[nt][1]));
                }
        }
    }

    // ---- epilogue: tanh, weight by w_e, row-reduce, atomic into g_energy ----
    const int b = tm >> 4;   // 16 M-tiles per batch
    __syncthreads();
    float* dp_s = (float*)&As[0][0];
    float* we_s = dp_s + BN;
    if (tid < BN) {
        dp_s[tid] = g_dp[b * ATT + tn * BN + tid];
        we_s[tid] = we_v[tn * BN + tid];
    }
    __syncthreads();

    const int r = lane >> 2, c = lane & 3;
    const float* dpp = dp_s + wn * 64;
    const float* wep = we_s + wn * 64;

#pragma unroll
    for (int mt = 0; mt < 2; mt++) {
#pragma unroll
        for (int rr = 0; rr < 2; rr++) {
            float rsum = 0.f;
#pragma unroll
            for (int nt = 0; nt < 8; nt++) {
#pragma unroll
                for (int cc = 0; cc < 2; cc++) {
                    const int col = nt * 8 + c * 2 + cc;
                    const float x = acc[mt][nt][rr * 2 + cc] + dpp[col];
                    rsum += tanhf(x) * wep[col];
                }
            }
            rsum += __shfl_xor_sync(0xffffffffu, rsum, 1);
            rsum += __shfl_xor_sync(0xffffffffu, rsum, 2);
            if (c == 0) {
                const int row = tm * BM + wm * 32 + mt * 16 + rr * 8 + r;
                atomicAdd(&g_energy[row], rsum);
            }
        }
    }
}

// ---------------------------------------------------------------------------
// Kernel 3a: masked softmax (mask = int32). Also zeroes out_ctx for 3b atomics.
// ---------------------------------------------------------------------------
__global__ void k_softmax(const int* __restrict__ mask,
                          float* __restrict__ out_w,
                          float* __restrict__ out_ctx) {
    const int b = blockIdx.x, t = threadIdx.x;
    __shared__ float red[32];
    const float NEG = __int_as_float(0xff800000);

    out_ctx[b * ENC2 + t] = 0.f;

    float e0 = g_energy[b * NS + t];
    float e1 = g_energy[b * NS + 1024 + t];
    bool m0 = mask[b * NS + t] != 0;
    bool m1 = mask[b * NS + 1024 + t] != 0;

    float v = fmaxf(m0 ? e0 : NEG, m1 ? e1 : NEG);
#pragma unroll
    for (int o = 16; o; o >>= 1) v = fmaxf(v, __shfl_xor_sync(0xffffffffu, v, o));
    if ((t & 31) == 0) red[t >> 5] = v;
    __syncthreads();
    if (t < 32) {
        float x = red[t];
#pragma unroll
        for (int o = 16; o; o >>= 1) x = fmaxf(x, __shfl_xor_sync(0xffffffffu, x, o));
        red[t] = x;
    }
    __syncthreads();
    const float mx = red[0];
    __syncthreads();

    float x0 = m0 ? __expf(e0 - mx) : 0.f;
    float x1 = m1 ? __expf(e1 - mx) : 0.f;
    float s = x0 + x1;
#pragma unroll
    for (int o = 16; o; o >>= 1) s += __shfl_xor_sync(0xffffffffu, s, o);
    if ((t & 31) == 0) red[t >> 5] = s;
    __syncthreads();
    if (t < 32) {
        float x = red[t];
#pragma unroll
        for (int o = 16; o; o >>= 1) x += __shfl_xor_sync(0xffffffffu, x, o);
        red[t] = x;
    }
    __syncthreads();
    const float inv = 1.0f / red[0];

    out_w[b * NS + t]        = x0 * inv;
    out_w[b * NS + 1024 + t] = x1 * inv;
}

// ---------------------------------------------------------------------------
// Kernel 3b: context, split-S x8 with atomics for MLP/occupancy.
// grid (32 b, 8 e-chunks, 8 s-chunks), 256 threads.
// ---------------------------------------------------------------------------
__global__ void k_context(const float* __restrict__ enc,
                          const float* __restrict__ w,
                          float* __restrict__ out_ctx) {
    const int b = blockIdx.x;
    const int e = blockIdx.y * 128 + (threadIdx.x & 127);
    const int stripe = threadIdx.x >> 7;
    const int s0 = blockIdx.z * 256;

    const float* wp = w + b * NS;
    const float* ep = enc + ((size_t)b * NS) * ENC2 + e;

    float a0 = 0.f, a1 = 0.f, a2 = 0.f, a3 = 0.f;
    for (int s = s0 + stripe; s < s0 + 256; s += 8) {
        a0 += wp[s]     * ep[(size_t)(s)     * ENC2];
        a1 += wp[s + 2] * ep[(size_t)(s + 2) * ENC2];
        a2 += wp[s + 4] * ep[(size_t)(s + 4) * ENC2];
        a3 += wp[s + 6] * ep[(size_t)(s + 6) * ENC2];
    }
    float acc = (a0 + a1) + (a2 + a3);

    __shared__ float part[128];
    if (stripe == 1) part[threadIdx.x & 127] = acc;
    __syncthreads();
    if (stripe == 0)
        atomicAdd(&out_ctx[b * ENC2 + e], acc + part[threadIdx.x]);
}

// ---------------------------------------------------------------------------
extern "C" void kernel_launch(void* const* d_in, const int* in_sizes, int n_in,
                              void* d_out, int out_size) {
    const float* dh    = (const float*)d_in[0];
    const float* enc   = (const float*)d_in[1];
    const int*   mask  = (const int*)d_in[2];
    const float* W_enc = (const float*)d_in[3];
    const float* b_enc = (const float*)d_in[4];
    const float* W_dec = (const float*)d_in[5];
    const float* b_dec = (const float*)d_in[6];
    const float* w_e   = (const float*)d_in[7];
    // d_in[8] = b_e : softmax-invariant, unused.

    float* out_ctx = (float*)d_out;
    float* out_w   = (float*)d_out + NB * ENC2;

    k_convert<<<2048, 256>>>(enc);
    k_transpose<<<dim3(32, 32), dim3(32, 8)>>>(W_enc);
    k_decproj<<<dim3(8, 4), 128>>>(dh, W_dec, b_dec, b_enc);
    k_energy<<<dim3(8, 512), 256>>>(w_e);
    k_softmax<<<32, 1024>>>(mask, out_w, out_ctx);
    k_context<<<dim3(32, 8, 8), 256>>>(enc, out_w, out_ctx);
}

// round 7
// speedup vs baseline: 1.8647x; 1.1160x over previous
#include <cuda_runtime.h>
#include <cuda_fp16.h>
#include <cstdint>

#define NB 32
#define NS 2048
#define ENC2 1024
#define DEC 1024
#define ATT 1024

#define BM 128
#define BN 128
#define BK 32          // K halfs per chunk
#define ASTRH 40       // smem row stride in halfs (80B): ldmatrix conflict-free
#define STG 4          // cp.async pipeline stages
#define STAGE_B (BM * ASTRH * 2)   // 10240 bytes per stage (per array)

// scratch (no allocations allowed)
__device__ float  g_dp[NB * ATT];                       // decoder_proj + b_dec + b_enc
__device__ float  g_energy[NB * NS];                    // energies (b_e dropped)
__device__ __half g_ench[(size_t)NB * NS * ENC2];       // enc in fp16 (128 MB)
__device__ __half g_Wth[ATT * ENC2];                    // W_enc^T in fp16: Wt[n][k]

__device__ __forceinline__ uint32_t smem_u32(const void* p) {
    uint32_t a;
    asm("{ .reg .u64 t; cvta.to.shared.u64 t, %1; cvt.u32.u64 %0, t; }"
        : "=r"(a) : "l"(p));
    return a;
}
__device__ __forceinline__ uint2 f4_to_h4(float4 v) {
    half2 lo = __float22half2_rn(make_float2(v.x, v.y));
    half2 hi = __float22half2_rn(make_float2(v.z, v.w));
    uint2 u;
    u.x = *(uint32_t*)&lo;
    u.y = *(uint32_t*)&hi;
    return u;
}

// ---------------------------------------------------------------------------
// Kernel 0a: enc fp32 -> fp16 (vectorized grid-stride)
// ---------------------------------------------------------------------------
__global__ void k_convert(const float* __restrict__ enc) {
    const size_t total4 = (size_t)NB * NS * ENC2 / 4;   // 16M float4
    uint2* dst = (uint2*)g_ench;
    const float4* src = (const float4*)enc;
    for (size_t p = (size_t)blockIdx.x * blockDim.x + threadIdx.x;
         p < total4; p += (size_t)gridDim.x * blockDim.x)
        dst[p] = f4_to_h4(src[p]);
}

// ---------------------------------------------------------------------------
// Kernel 0b: transpose W_enc into g_Wth (n-major, k contiguous, fp16)
// ---------------------------------------------------------------------------
__global__ void k_transpose(const float* __restrict__ W) {
    __shared__ float t[32][33];
    const int x = blockIdx.x * 32 + threadIdx.x;   // n
    const int y0 = blockIdx.y * 32;                // k base
    for (int j = threadIdx.y; j < 32; j += 8)
        t[j][threadIdx.x] = W[(y0 + j) * ATT + x];
    __syncthreads();
    const int k = blockIdx.y * 32 + threadIdx.x;
    const int n0 = blockIdx.x * 32;
    for (int j = threadIdx.y; j < 32; j += 8)
        g_Wth[(size_t)(n0 + j) * ENC2 + k] = __float2half(t[threadIdx.x][j]);
}

// ---------------------------------------------------------------------------
// Kernel 1: dec_proj + bias fold; also zero g_energy (graph-replay clean).
// ---------------------------------------------------------------------------
__global__ void k_decproj(const float* __restrict__ dh,
                          const float* __restrict__ Wd,
                          const float* __restrict__ bd,
                          const float* __restrict__ ben) {
    __shared__ float sdh[8][DEC];
    const int a  = blockIdx.x * 128 + threadIdx.x;
    const int b0 = blockIdx.y * 8;

    for (int i = threadIdx.x; i < 8 * DEC; i += 128)
        sdh[i >> 10][i & 1023] = dh[(b0 + (i >> 10)) * DEC + (i & 1023)];
    __syncthreads();

    float acc[8];
#pragma unroll
    for (int bb = 0; bb < 8; bb++) acc[bb] = 0.f;
#pragma unroll 4
    for (int d = 0; d < DEC; d++) {
        const float w = Wd[d * ATT + a];
#pragma unroll
        for (int bb = 0; bb < 8; bb++) acc[bb] += w * sdh[bb][d];
    }
    const float bias = bd[a] + ben[a];
#pragma unroll
    for (int bb = 0; bb < 8; bb++)
        g_dp[(b0 + bb) * ATT + a] = acc[bb] + bias;

    const int tid = (blockIdx.y * gridDim.x + blockIdx.x) * 128 + threadIdx.x;
    for (int i = tid; i < NB * NS; i += 32 * 128) g_energy[i] = 0.f;
}

// ---------------------------------------------------------------------------
// Kernel 2: fused energy GEMM, fp16 mma.sync + ldmatrix + 4-stage cp.async.
// CTA 128x128, K-chunk 32, 8 warps (4x2), 2 CTAs/SM, tn fastest.
// ---------------------------------------------------------------------------
__global__ __launch_bounds__(256, 2)
void k_energy(const float* __restrict__ we_v) {
    __shared__ __align__(16) __half As[STG][BM * ASTRH];
    __shared__ __align__(16) __half Bs[STG][BN * ASTRH];

    const int tn = blockIdx.x;                  // 0..7   N tile (fastest)
    const int tm = blockIdx.y;                  // 0..511 M tile
    const int tid  = threadIdx.x;
    const int lane = tid & 31;
    const int warp = tid >> 5;
    const int wm = warp >> 1;                   // 0..3
    const int wn = warp & 1;                    // 0..1

    const __half* Ag = g_ench + (size_t)tm * BM * ENC2;
    const __half* Bg = g_Wth + (size_t)tn * BN * ENC2;

    float acc[2][8][4];
#pragma unroll
    for (int i = 0; i < 2; i++)
#pragma unroll
        for (int j = 0; j < 8; j++)
#pragma unroll
            for (int k = 0; k < 4; k++) acc[i][j][k] = 0.f;

    // ldmatrix per-lane base addresses (stage 0):
    // A x4 tile (16x16) at (wm*32 + mt*16, 16*ks):
    //   lanes 0-7: rows 0-7 k-lo | 8-15: rows 8-15 k-lo | 16-23: rows 0-7 k-hi | 24-31: rows 8-15 k-hi
    const uint32_t aBase = smem_u32(&As[0][0])
        + (uint32_t)((wm * 32 + (lane & 15)) * (ASTRH * 2))
        + (uint32_t)(((lane >> 4) & 1) * 16);
    // B x4: matrices (nt=2p,klo)(2p,khi)(2p+1,klo)(2p+1,khi):
    //   lane -> n row: wn*64 + p*16 + ((lane>>4)&1)*8 + (lane&7); k-half: (lane>>3)&1
    const uint32_t bBase = smem_u32(&Bs[0][0])
        + (uint32_t)((wn * 64 + ((lane >> 4) & 1) * 8 + (lane & 7)) * (ASTRH * 2))
        + (uint32_t)(((lane >> 3) & 1) * 16);

    // loader: per chunk, 512 x 16B for A + 512 x 16B for B over 256 threads
    auto load_chunk = [&](int kc) {
        const int st = kc & (STG - 1);
        const __half* a = Ag + kc * BK;
        const __half* b = Bg + kc * BK;
#pragma unroll
        for (int j = 0; j < 2; j++) {
            const int idx = tid + j * 256;          // 0..511
            const int row = idx >> 2, c16 = idx & 3;
            const uint32_t da = smem_u32(&As[st][row * ASTRH + c16 * 8]);
            asm volatile("cp.async.cg.shared.global [%0], [%1], 16;"
                         :: "r"(da), "l"(a + (size_t)row * ENC2 + c16 * 8));
            const uint32_t db = smem_u32(&Bs[st][row * ASTRH + c16 * 8]);
            asm volatile("cp.async.cg.shared.global [%0], [%1], 16;"
                         :: "r"(db), "l"(b + (size_t)row * ENC2 + c16 * 8));
        }
        asm volatile("cp.async.commit_group;" ::: "memory");
    };

    load_chunk(0);
    load_chunk(1);
    load_chunk(2);

    const int NKT = ENC2 / BK;  // 32
    for (int kt = 0; kt < NKT; kt++) {
        if (kt < NKT - 2)
            asm volatile("cp.async.wait_group 2;" ::: "memory");
        else if (kt == NKT - 2)
            asm volatile("cp.async.wait_group 1;" ::: "memory");
        else
            asm volatile("cp.async.wait_group 0;" ::: "memory");
        __syncthreads();

        if (kt + 3 < NKT) load_chunk(kt + 3);

        const uint32_t stOff = (uint32_t)((kt & (STG - 1)) * STAGE_B);
        const uint32_t aAddr = aBase + stOff;
        const uint32_t bAddr = bBase + stOff;

#pragma unroll
        for (int ks = 0; ks < 2; ks++) {
            uint32_t af[2][4];
#pragma unroll
            for (int mt = 0; mt < 2; mt++) {
                asm volatile(
                    "ldmatrix.sync.aligned.m8n8.x4.shared.b16 {%0,%1,%2,%3}, [%4];"
                    : "=r"(af[mt][0]), "=r"(af[mt][1]), "=r"(af[mt][2]), "=r"(af[mt][3])
                    : "r"(aAddr + (uint32_t)(mt * 16 * ASTRH * 2 + ks * 32)));
            }
            uint32_t bf[8][2];
#pragma unroll
            for (int p = 0; p < 4; p++) {
                asm volatile(
                    "ldmatrix.sync.aligned.m8n8.x4.shared.b16 {%0,%1,%2,%3}, [%4];"
                    : "=r"(bf[2 * p][0]), "=r"(bf[2 * p][1]),
                      "=r"(bf[2 * p + 1][0]), "=r"(bf[2 * p + 1][1])
                    : "r"(bAddr + (uint32_t)(p * 16 * ASTRH * 2 + ks * 32)));
            }
#pragma unroll
            for (int mt = 0; mt < 2; mt++)
#pragma unroll
                for (int nt = 0; nt < 8; nt++) {
                    float* d = acc[mt][nt];
                    asm volatile(
                        "mma.sync.aligned.m16n8k16.row.col.f32.f16.f16.f32 "
                        "{%0,%1,%2,%3}, {%4,%5,%6,%7}, {%8,%9}, {%0,%1,%2,%3};"
                        : "+f"(d[0]), "+f"(d[1]), "+f"(d[2]), "+f"(d[3])
                        : "r"(af[mt][0]), "r"(af[mt][1]), "r"(af[mt][2]), "r"(af[mt][3]),
                          "r"(bf[nt][0]), "r"(bf[nt][1]));
                }
        }
    }

    // ---- epilogue: tanh, weight by w_e, row-reduce, atomic into g_energy ----
    const int b = tm >> 4;   // 16 M-tiles per batch
    __syncthreads();
    float* dp_s = (float*)&As[0][0];
    float* we_s = dp_s + BN;
    if (tid < BN) {
        dp_s[tid] = g_dp[b * ATT + tn * BN + tid];
        we_s[tid] = we_v[tn * BN + tid];
    }
    __syncthreads();

    const int r = lane >> 2, c = lane & 3;
    const float* dpp = dp_s + wn * 64;
    const float* wep = we_s + wn * 64;

#pragma unroll
    for (int mt = 0; mt < 2; mt++) {
#pragma unroll
        for (int rr = 0; rr < 2; rr++) {
            float rsum = 0.f;
#pragma unroll
            for (int nt = 0; nt < 8; nt++) {
#pragma unroll
                for (int cc = 0; cc < 2; cc++) {
                    const int col = nt * 8 + c * 2 + cc;
                    const float x = acc[mt][nt][rr * 2 + cc] + dpp[col];
                    rsum += tanhf(x) * wep[col];
                }
            }
            rsum += __shfl_xor_sync(0xffffffffu, rsum, 1);
            rsum += __shfl_xor_sync(0xffffffffu, rsum, 2);
            if (c == 0) {
                const int row = tm * BM + wm * 32 + mt * 16 + rr * 8 + r;
                atomicAdd(&g_energy[row], rsum);
            }
        }
    }
}

// ---------------------------------------------------------------------------
// Kernel 3a: masked softmax (mask = int32). Also zeroes out_ctx for 3b atomics.
// ---------------------------------------------------------------------------
__global__ void k_softmax(const int* __restrict__ mask,
                          float* __restrict__ out_w,
                          float* __restrict__ out_ctx) {
    const int b = blockIdx.x, t = threadIdx.x;
    __shared__ float red[32];
    const float NEG = __int_as_float(0xff800000);

    out_ctx[b * ENC2 + t] = 0.f;

    float e0 = g_energy[b * NS + t];
    float e1 = g_energy[b * NS + 1024 + t];
    bool m0 = mask[b * NS + t] != 0;
    bool m1 = mask[b * NS + 1024 + t] != 0;

    float v = fmaxf(m0 ? e0 : NEG, m1 ? e1 : NEG);
#pragma unroll
    for (int o = 16; o; o >>= 1) v = fmaxf(v, __shfl_xor_sync(0xffffffffu, v, o));
    if ((t & 31) == 0) red[t >> 5] = v;
    __syncthreads();
    if (t < 32) {
        float x = red[t];
#pragma unroll
        for (int o = 16; o; o >>= 1) x = fmaxf(x, __shfl_xor_sync(0xffffffffu, x, o));
        red[t] = x;
    }
    __syncthreads();
    const float mx = red[0];
    __syncthreads();

    float x0 = m0 ? __expf(e0 - mx) : 0.f;
    float x1 = m1 ? __expf(e1 - mx) : 0.f;
    float s = x0 + x1;
#pragma unroll
    for (int o = 16; o; o >>= 1) s += __shfl_xor_sync(0xffffffffu, s, o);
    if ((t & 31) == 0) red[t >> 5] = s;
    __syncthreads();
    if (t < 32) {
        float x = red[t];
#pragma unroll
        for (int o = 16; o; o >>= 1) x += __shfl_xor_sync(0xffffffffu, x, o);
        red[t] = x;
    }
    __syncthreads();
    const float inv = 1.0f / red[0];

    out_w[b * NS + t]        = x0 * inv;
    out_w[b * NS + 1024 + t] = x1 * inv;
}

// ---------------------------------------------------------------------------
// Kernel 3b: context from fp16 enc (half the DRAM traffic), split-S x8.
// grid (32 b, 8 e-chunks, 8 s-chunks), 256 threads.
// ---------------------------------------------------------------------------
__global__ void k_context(const float* __restrict__ w,
                          float* __restrict__ out_ctx) {
    const int b = blockIdx.x;
    const int e = blockIdx.y * 128 + (threadIdx.x & 127);
    const int stripe = threadIdx.x >> 7;
    const int s0 = blockIdx.z * 256;

    const float* wp = w + b * NS;
    const __half* ep = g_ench + ((size_t)b * NS) * ENC2 + e;

    float a0 = 0.f, a1 = 0.f, a2 = 0.f, a3 = 0.f;
    for (int s = s0 + stripe; s < s0 + 256; s += 8) {
        a0 += wp[s]     * __half2float(ep[(size_t)(s)     * ENC2]);
        a1 += wp[s + 2] * __half2float(ep[(size_t)(s + 2) * ENC2]);
        a2 += wp[s + 4] * __half2float(ep[(size_t)(s + 4) * ENC2]);
        a3 += wp[s + 6] * __half2float(ep[(size_t)(s + 6) * ENC2]);
    }
    float acc = (a0 + a1) + (a2 + a3);

    __shared__ float part[128];
    if (stripe == 1) part[threadIdx.x & 127] = acc;
    __syncthreads();
    if (stripe == 0)
        atomicAdd(&out_ctx[b * ENC2 + e], acc + part[threadIdx.x]);
}

// ---------------------------------------------------------------------------
extern "C" void kernel_launch(void* const* d_in, const int* in_sizes, int n_in,
                              void* d_out, int out_size) {
    const float* dh    = (const float*)d_in[0];
    const float* enc   = (const float*)d_in[1];
    const int*   mask  = (const int*)d_in[2];
    const float* W_enc = (const float*)d_in[3];
    const float* b_enc = (const float*)d_in[4];
    const float* W_dec = (const float*)d_in[5];
    const float* b_dec = (const float*)d_in[6];
    const float* w_e   = (const float*)d_in[7];
    // d_in[8] = b_e : softmax-invariant, unused.

    float* out_ctx = (float*)d_out;
    float* out_w   = (float*)d_out + NB * ENC2;

    k_convert<<<2048, 256>>>(enc);
    k_transpose<<<dim3(32, 32), dim3(32, 8)>>>(W_enc);
    k_decproj<<<dim3(8, 4), 128>>>(dh, W_dec, b_dec, b_enc);
    k_energy<<<dim3(8, 512), 256>>>(w_e);
    k_softmax<<<32, 1024>>>(mask, out_w, out_ctx);
    k_context<<<dim3(32, 8, 8), 256>>>(out_w, out_ctx);
}

// round 8
// speedup vs baseline: 2.0138x; 1.0799x over previous
#include <cuda_runtime.h>
#include <cuda_fp16.h>
#include <cstdint>

#define NB 32
#define NS 2048
#define ENC2 1024
#define DEC 1024
#define ATT 1024

#define BM 128
#define BN 128
#define BK 64                       // K halfs per chunk (halves barrier count)
#define ASTRH 72                    // smem row stride in halfs (144B): ldmatrix conflict-free
#define STG 3                       // cp.async pipeline stages
#define STAGE_H (BM * ASTRH)        // halfs per stage per array (9216)
#define STAGE_B (STAGE_H * 2)       // 18432 bytes
#define SMEM_DYN (STG * STAGE_B * 2)  // 110592 bytes

// scratch (no allocations allowed)
__device__ float  g_dp[NB * ATT];                       // decoder_proj + b_dec + b_enc
__device__ float  g_energy[NB * NS];                    // energies (b_e dropped)
__device__ __half g_ench[(size_t)NB * NS * ENC2];       // enc in fp16 (128 MB)
__device__ __half g_Wth[ATT * ENC2];                    // W_enc^T in fp16: Wt[n][k]

__device__ __forceinline__ uint32_t smem_u32(const void* p) {
    uint32_t a;
    asm("{ .reg .u64 t; cvta.to.shared.u64 t, %1; cvt.u32.u64 %0, t; }"
        : "=r"(a) : "l"(p));
    return a;
}
__device__ __forceinline__ uint2 f4_to_h4(float4 v) {
    half2 lo = __float22half2_rn(make_float2(v.x, v.y));
    half2 hi = __float22half2_rn(make_float2(v.z, v.w));
    uint2 u;
    u.x = *(uint32_t*)&lo;
    u.y = *(uint32_t*)&hi;
    return u;
}

// ---------------------------------------------------------------------------
// Kernel 0a: enc fp32 -> fp16 (vectorized grid-stride)
// ---------------------------------------------------------------------------
__global__ void k_convert(const float* __restrict__ enc) {
    const size_t total4 = (size_t)NB * NS * ENC2 / 4;   // 16M float4
    uint2* dst = (uint2*)g_ench;
    const float4* src = (const float4*)enc;
    for (size_t p = (size_t)blockIdx.x * blockDim.x + threadIdx.x;
         p < total4; p += (size_t)gridDim.x * blockDim.x)
        dst[p] = f4_to_h4(src[p]);
}

// ---------------------------------------------------------------------------
// Kernel 0b: transpose W_enc into g_Wth (n-major, k contiguous, fp16)
// ---------------------------------------------------------------------------
__global__ void k_transpose(const float* __restrict__ W) {
    __shared__ float t[32][33];
    const int x = blockIdx.x * 32 + threadIdx.x;   // n
    const int y0 = blockIdx.y * 32;                // k base
    for (int j = threadIdx.y; j < 32; j += 8)
        t[j][threadIdx.x] = W[(y0 + j) * ATT + x];
    __syncthreads();
    const int k = blockIdx.y * 32 + threadIdx.x;
    const int n0 = blockIdx.x * 32;
    for (int j = threadIdx.y; j < 32; j += 8)
        g_Wth[(size_t)(n0 + j) * ENC2 + k] = __float2half(t[threadIdx.x][j]);
}

// ---------------------------------------------------------------------------
// Kernel 1: dec_proj + bias fold; also zero g_energy (graph-replay clean).
// ---------------------------------------------------------------------------
__global__ void k_decproj(const float* __restrict__ dh,
                          const float* __restrict__ Wd,
                          const float* __restrict__ bd,
                          const float* __restrict__ ben) {
    __shared__ float sdh[8][DEC];
    const int a  = blockIdx.x * 128 + threadIdx.x;
    const int b0 = blockIdx.y * 8;

    for (int i = threadIdx.x; i < 8 * DEC; i += 128)
        sdh[i >> 10][i & 1023] = dh[(b0 + (i >> 10)) * DEC + (i & 1023)];
    __syncthreads();

    float acc[8];
#pragma unroll
    for (int bb = 0; bb < 8; bb++) acc[bb] = 0.f;
#pragma unroll 4
    for (int d = 0; d < DEC; d++) {
        const float w = Wd[d * ATT + a];
#pragma unroll
        for (int bb = 0; bb < 8; bb++) acc[bb] += w * sdh[bb][d];
    }
    const float bias = bd[a] + ben[a];
#pragma unroll
    for (int bb = 0; bb < 8; bb++)
        g_dp[(b0 + bb) * ATT + a] = acc[bb] + bias;

    const int tid = (blockIdx.y * gridDim.x + blockIdx.x) * 128 + threadIdx.x;
    for (int i = tid; i < NB * NS; i += 32 * 128) g_energy[i] = 0.f;
}

// ---------------------------------------------------------------------------
// Kernel 2: fused energy GEMM, fp16 mma.sync + ldmatrix + 3-stage cp.async.
// CTA 128x128, K-chunk 64 (16 barriers), 8 warps (4x2), 2 CTAs/SM, tn fastest.
// ---------------------------------------------------------------------------
__global__ __launch_bounds__(256, 2)
void k_energy(const float* __restrict__ we_v) {
    extern __shared__ __align__(16) __half sh[];
    __half* As = sh;                     // [STG][STAGE_H]
    __half* Bs = sh + STG * STAGE_H;     // [STG][STAGE_H]

    const int tn = blockIdx.x;                  // 0..7   N tile (fastest)
    const int tm = blockIdx.y;                  // 0..511 M tile
    const int tid  = threadIdx.x;
    const int lane = tid & 31;
    const int warp = tid >> 5;
    const int wm = warp >> 1;                   // 0..3
    const int wn = warp & 1;                    // 0..1

    float acc[2][8][4];
#pragma unroll
    for (int i = 0; i < 2; i++)
#pragma unroll
        for (int j = 0; j < 8; j++)
#pragma unroll
            for (int k = 0; k < 4; k++) acc[i][j][k] = 0.f;

    // hoisted loader coordinates: 1024 x 16B per array per chunk, 4 per thread
    // idx = tid + j*256; row = idx>>3 (0..127), c16 = idx&7
    size_t srcOff[4];
    uint32_t dstOff[4];
#pragma unroll
    for (int j = 0; j < 4; j++) {
        const int idx = tid + j * 256;
        const int row = idx >> 3, c16 = idx & 7;
        srcOff[j] = (size_t)row * ENC2 + c16 * 8;
        dstOff[j] = (uint32_t)(row * ASTRH + c16 * 8) * 2;
    }
    const __half* Ag = g_ench + (size_t)tm * BM * ENC2;
    const __half* Bg = g_Wth + (size_t)tn * BN * ENC2;
    const uint32_t asBase = smem_u32(As);
    const uint32_t bsBase = smem_u32(Bs);

    auto load_chunk = [&](int kc) {
        const int st = kc - (kc / STG) * STG;           // kc % 3
        const __half* a = Ag + kc * BK;
        const __half* b = Bg + kc * BK;
        const uint32_t sA = asBase + st * STAGE_B;
        const uint32_t sB = bsBase + st * STAGE_B;
#pragma unroll
        for (int j = 0; j < 4; j++) {
            asm volatile("cp.async.cg.shared.global [%0], [%1], 16;"
                         :: "r"(sA + dstOff[j]), "l"(a + srcOff[j]));
            asm volatile("cp.async.cg.shared.global [%0], [%1], 16;"
                         :: "r"(sB + dstOff[j]), "l"(b + srcOff[j]));
        }
        asm volatile("cp.async.commit_group;" ::: "memory");
    };

    // ldmatrix per-lane base addresses (stage 0):
    const uint32_t aBase = asBase
        + (uint32_t)((wm * 32 + (lane & 15)) * (ASTRH * 2))
        + (uint32_t)(((lane >> 4) & 1) * 16);
    const uint32_t bBase = bsBase
        + (uint32_t)((wn * 64 + ((lane >> 4) & 1) * 8 + (lane & 7)) * (ASTRH * 2))
        + (uint32_t)(((lane >> 3) & 1) * 16);

    load_chunk(0);
    load_chunk(1);

    const int NKT = ENC2 / BK;  // 16
    for (int kt = 0; kt < NKT; kt++) {
        if (kt < NKT - 1)
            asm volatile("cp.async.wait_group 1;" ::: "memory");
        else
            asm volatile("cp.async.wait_group 0;" ::: "memory");
        __syncthreads();   // chunk kt visible; stage (kt+2)%3 readers (iter kt-1) done

        if (kt + 2 < NKT) load_chunk(kt + 2);

        const int st = kt - (kt / STG) * STG;
        const uint32_t stOff = (uint32_t)(st * STAGE_B);
        const uint32_t aAddr = aBase + stOff;
        const uint32_t bAddr = bBase + stOff;

#pragma unroll
        for (int ks = 0; ks < 4; ks++) {       // four k16 steps per 64-chunk
            uint32_t af[2][4];
#pragma unroll
            for (int mt = 0; mt < 2; mt++) {
                asm volatile(
                    "ldmatrix.sync.aligned.m8n8.x4.shared.b16 {%0,%1,%2,%3}, [%4];"
                    : "=r"(af[mt][0]), "=r"(af[mt][1]), "=r"(af[mt][2]), "=r"(af[mt][3])
                    : "r"(aAddr + (uint32_t)(mt * 16 * ASTRH * 2 + ks * 32)));
            }
            uint32_t bf[8][2];
#pragma unroll
            for (int p = 0; p < 4; p++) {
                asm volatile(
                    "ldmatrix.sync.aligned.m8n8.x4.shared.b16 {%0,%1,%2,%3}, [%4];"
                    : "=r"(bf[2 * p][0]), "=r"(bf[2 * p][1]),
                      "=r"(bf[2 * p + 1][0]), "=r"(bf[2 * p + 1][1])
                    : "r"(bAddr + (uint32_t)(p * 16 * ASTRH * 2 + ks * 32)));
            }
#pragma unroll
            for (int mt = 0; mt < 2; mt++)
#pragma unroll
                for (int nt = 0; nt < 8; nt++) {
                    float* d = acc[mt][nt];
                    asm volatile(
                        "mma.sync.aligned.m16n8k16.row.col.f32.f16.f16.f32 "
                        "{%0,%1,%2,%3}, {%4,%5,%6,%7}, {%8,%9}, {%0,%1,%2,%3};"
                        : "+f"(d[0]), "+f"(d[1]), "+f"(d[2]), "+f"(d[3])
                        : "r"(af[mt][0]), "r"(af[mt][1]), "r"(af[mt][2]), "r"(af[mt][3]),
                          "r"(bf[nt][0]), "r"(bf[nt][1]));
                }
        }
    }

    // ---- epilogue: tanh, weight by w_e, row-reduce, atomic into g_energy ----
    const int b = tm >> 4;   // 16 M-tiles per batch
    __syncthreads();
    float* dp_s = (float*)As;
    float* we_s = dp_s + BN;
    if (tid < BN) {
        dp_s[tid] = g_dp[b * ATT + tn * BN + tid];
        we_s[tid] = we_v[tn * BN + tid];
    }
    __syncthreads();

    const int r = lane >> 2, c = lane & 3;
    const float* dpp = dp_s + wn * 64;
    const float* wep = we_s + wn * 64;

#pragma unroll
    for (int mt = 0; mt < 2; mt++) {
#pragma unroll
        for (int rr = 0; rr < 2; rr++) {
            float rsum = 0.f;
#pragma unroll
            for (int nt = 0; nt < 8; nt++) {
#pragma unroll
                for (int cc = 0; cc < 2; cc++) {
                    const int col = nt * 8 + c * 2 + cc;
                    const float x = acc[mt][nt][rr * 2 + cc] + dpp[col];
                    rsum += tanhf(x) * wep[col];
                }
            }
            rsum += __shfl_xor_sync(0xffffffffu, rsum, 1);
            rsum += __shfl_xor_sync(0xffffffffu, rsum, 2);
            if (c == 0) {
                const int row = tm * BM + wm * 32 + mt * 16 + rr * 8 + r;
                atomicAdd(&g_energy[row], rsum);
            }
        }
    }
}

// ---------------------------------------------------------------------------
// Kernel 3a: masked softmax (mask = int32). Also zeroes out_ctx for 3b atomics.
// ---------------------------------------------------------------------------
__global__ void k_softmax(const int* __restrict__ mask,
                          float* __restrict__ out_w,
                          float* __restrict__ out_ctx) {
    const int b = blockIdx.x, t = threadIdx.x;
    __shared__ float red[32];
    const float NEG = __int_as_float(0xff800000);

    out_ctx[b * ENC2 + t] = 0.f;

    float e0 = g_energy[b * NS + t];
    float e1 = g_energy[b * NS + 1024 + t];
    bool m0 = mask[b * NS + t] != 0;
    bool m1 = mask[b * NS + 1024 + t] != 0;

    float v = fmaxf(m0 ? e0 : NEG, m1 ? e1 : NEG);
#pragma unroll
    for (int o = 16; o; o >>= 1) v = fmaxf(v, __shfl_xor_sync(0xffffffffu, v, o));
    if ((t & 31) == 0) red[t >> 5] = v;
    __syncthreads();
    if (t < 32) {
        float x = red[t];
#pragma unroll
        for (int o = 16; o; o >>= 1) x = fmaxf(x, __shfl_xor_sync(0xffffffffu, x, o));
        red[t] = x;
    }
    __syncthreads();
    const float mx = red[0];
    __syncthreads();

    float x0 = m0 ? __expf(e0 - mx) : 0.f;
    float x1 = m1 ? __expf(e1 - mx) : 0.f;
    float s = x0 + x1;
#pragma unroll
    for (int o = 16; o; o >>= 1) s += __shfl_xor_sync(0xffffffffu, s, o);
    if ((t & 31) == 0) red[t >> 5] = s;
    __syncthreads();
    if (t < 32) {
        float x = red[t];
#pragma unroll
        for (int o = 16; o; o >>= 1) x += __shfl_xor_sync(0xffffffffu, x, o);
        red[t] = x;
    }
    __syncthreads();
    const float inv = 1.0f / red[0];

    out_w[b * NS + t]        = x0 * inv;
    out_w[b * NS + 1024 + t] = x1 * inv;
}

// ---------------------------------------------------------------------------
// Kernel 3b: context from fp16 enc, split-S x8 with atomics.
// grid (32 b, 8 e-chunks, 8 s-chunks), 256 threads.
// ---------------------------------------------------------------------------
__global__ void k_context(const float* __restrict__ w,
                          float* __restrict__ out_ctx) {
    const int b = blockIdx.x;
    const int e = blockIdx.y * 128 + (threadIdx.x & 127);
    const int stripe = threadIdx.x >> 7;
    const int s0 = blockIdx.z * 256;

    const float* wp = w + b * NS;
    const __half* ep = g_ench + ((size_t)b * NS) * ENC2 + e;

    float a0 = 0.f, a1 = 0.f, a2 = 0.f, a3 = 0.f;
    for (int s = s0 + stripe; s < s0 + 256; s += 8) {
        a0 += wp[s]     * __half2float(ep[(size_t)(s)     * ENC2]);
        a1 += wp[s + 2] * __half2float(ep[(size_t)(s + 2) * ENC2]);
        a2 += wp[s + 4] * __half2float(ep[(size_t)(s + 4) * ENC2]);
        a3 += wp[s + 6] * __half2float(ep[(size_t)(s + 6) * ENC2]);
    }
    float acc = (a0 + a1) + (a2 + a3);

    __shared__ float part[128];
    if (stripe == 1) part[threadIdx.x & 127] = acc;
    __syncthreads();
    if (stripe == 0)
        atomicAdd(&out_ctx[b * ENC2 + e], acc + part[threadIdx.x]);
}

// ---------------------------------------------------------------------------
extern "C" void kernel_launch(void* const* d_in, const int* in_sizes, int n_in,
                              void* d_out, int out_size) {
    const float* dh    = (const float*)d_in[0];
    const float* enc   = (const float*)d_in[1];
    const int*   mask  = (const int*)d_in[2];
    const float* W_enc = (const float*)d_in[3];
    const float* b_enc = (const float*)d_in[4];
    const float* W_dec = (const float*)d_in[5];
    const float* b_dec = (const float*)d_in[6];
    const float* w_e   = (const float*)d_in[7];
    // d_in[8] = b_e : softmax-invariant, unused.

    float* out_ctx = (float*)d_out;
    float* out_w   = (float*)d_out + NB * ENC2;

    cudaFuncSetAttribute(k_energy, cudaFuncAttributeMaxDynamicSharedMemorySize,
                         SMEM_DYN);

    k_convert<<<2048, 256>>>(enc);
    k_transpose<<<dim3(32, 32), dim3(32, 8)>>>(W_enc);
    k_decproj<<<dim3(8, 4), 128>>>(dh, W_dec, b_dec, b_enc);
    k_energy<<<dim3(8, 512), 256, SMEM_DYN>>>(w_e);
    k_softmax<<<32, 1024>>>(mask, out_w, out_ctx);
    k_context<<<dim3(32, 8, 8), 256>>>(out_w, out_ctx);
}